// round 4
// baseline (speedup 1.0000x reference)
#include <cuda_runtime.h>

#define RES 300
#define NCH 64            // NC_A + NC_D
#define NC_A 48
#define APP_DIM 27
#define SPB 64            // samples per block
#define BLOCK 256

// Scratch (zero-initialized device globals; pads never written -> stay 0)
__device__ float g_plane_t[3 * RES * RES * NCH + 64];  // (i, h, w, c) + pad
__device__ float g_line_t[3 * RES * NCH + 64];         // (i, h, c)    + pad

// ---------------------------------------------------------------------------
// Merged transpose: plane (3,64,300,300)->(3,300,300,64), line -> (3,300,64)
// ---------------------------------------------------------------------------
__global__ void transpose_kernel(const float* __restrict__ plane,
                                 const float* __restrict__ line) {
    int ih = blockIdx.x;            // 0..899
    int i = ih / RES, h = ih % RES;

    if (blockIdx.y == 10) {
        if (threadIdx.x < NCH)
            g_line_t[((size_t)i * RES + h) * NCH + threadIdx.x] =
                line[((size_t)i * NCH + threadIdx.x) * RES + h];
        return;
    }

    int w0 = blockIdx.y * 30;
    __shared__ float tile[NCH][31];

    for (int idx = threadIdx.x; idx < NCH * 30; idx += blockDim.x) {
        int c = idx / 30, w = idx % 30;
        tile[c][w] = plane[(((size_t)i * NCH + c) * RES + h) * RES + w0 + w];
    }
    __syncthreads();
    float* dst = g_plane_t + (((size_t)i * RES + h) * RES + w0) * NCH;
    for (int idx = threadIdx.x; idx < NCH * 30; idx += blockDim.x) {
        int w = idx / NCH, c = idx % NCH;
        dst[(size_t)w * NCH + c] = tile[c][w];
    }
}

// ---------------------------------------------------------------------------
// Fused kernel:
//   phase 1: one WARP per sample (8 samples/warp); 9 coalesced 512B loads,
//            shfl_xor(16) cross-half blend, f -> smem
//   phase 2: FOUR threads per sample; thread q computes outputs q*7..q*7+6
//            from a q-local padded W slice; density via quad + shfl reduce
// smem (floats): xyz[192] | Wq[4*1156] | Fsm[64*196]
//   Wq section per q: 144 rows x 8 cols (col e = basisW[q*7+e][j], e<7 & d<27
//   else 0); +4 pad floats so q-sections start 4 banks apart.
// ---------------------------------------------------------------------------
#define XYZ_OFF 0
#define WQ_OFF  192
#define WQ_SEC  1156                            // 144*8 + 4 pad
#define F_OFF   (WQ_OFF + 4 * WQ_SEC)           // 4816
#define SMEM_FLOATS (F_OFF + SPB * 196)         // 17360 -> 69440 bytes
#define F_ROW4  49                              // 196/4 float4 per row

__global__ void __launch_bounds__(BLOCK, 3)
fused_kernel(const float* __restrict__ xyz,
             const float* __restrict__ basisW,   // (27, 144) row-major
             float* __restrict__ out, int N)
{
    extern __shared__ __align__(16) float sm[];
    float*  xyzsm = sm + XYZ_OFF;
    float*  Wq    = sm + WQ_OFF;
    float*  Fraw  = sm + F_OFF;        // reused: W staging, then features
    float4* F4    = (float4*)(sm + F_OFF);

    const int tid = threadIdx.x;
    const long base = (long)blockIdx.x * SPB;

    // ---- phase 0a: coalesced raw W copy (into F area) + xyz ----
    for (int idx = tid; idx < APP_DIM * 144; idx += BLOCK)
        Fraw[idx] = basisW[idx];
    for (int idx = tid; idx < 3 * SPB; idx += BLOCK) {
        long g = base * 3 + idx;
        xyzsm[idx] = (g < (long)3 * N) ? xyz[g] : 0.f;
    }
    __syncthreads();

    // ---- phase 0b: permute W into per-q padded sections ----
    for (int idx = tid; idx < 4 * WQ_SEC; idx += BLOCK) {
        int q = idx / WQ_SEC, r = idx - q * WQ_SEC;
        float v = 0.f;
        if (r < 1152) {
            int j = r >> 3, e = r & 7, d = q * 7 + e;
            if (e < 7 && d < APP_DIM) v = Fraw[d * 144 + j];
        }
        Wq[idx] = v;
    }
    __syncthreads();

    // ---- phase 1: warp-per-sample gather/blend ----
    const float4* GP = (const float4*)g_plane_t;
    const float4* GL = (const float4*)g_line_t;
    const int lane = tid & 31;
    const int wrp  = tid >> 5;          // 0..7
    const int xh   = lane >> 4;         // 0/1: x (and z) half
    const int c4   = lane & 15;         // channel quad

#pragma unroll 1
    for (int s = wrp; s < SPB; s += 8) {
        float cx = xyzsm[s * 3 + 0];
        float cy = xyzsm[s * 3 + 1];
        float cz = xyzsm[s * 3 + 2];

        float4 av[3], bv[3], lv[3];
        float  wxv[3], wyv[3], wzv[3];

#pragma unroll
        for (int i = 0; i < 3; i++) {
            // MAT_MODE = {0,1},{0,2},{1,2}; VEC_MODE = {2,1,0}
            float gx = (i == 2) ? cy : cx;
            float gy = (i == 0) ? cy : cz;
            float gz = (i == 0) ? cz : ((i == 1) ? cy : cx);

            float ix = (gx + 1.f) * 0.5f * (float)(RES - 1);
            float iy = (gy + 1.f) * 0.5f * (float)(RES - 1);
            float iz = (gz + 1.f) * 0.5f * (float)(RES - 1);
            float x0f = floorf(ix), y0f = floorf(iy), z0f = floorf(iz);
            int x0 = (int)x0f, y0 = (int)y0f, z0 = (int)z0f;
            float wx = ix - x0f, wy = iy - y0f, wz = iz - z0f;
            int y1 = y0 + 1;
            if (y1 > RES - 1) { y1 = RES - 1; wy = 0.f; }
            if (x0 + 1 > RES - 1) wx = 0.f;   // xh=1 reads pad, weight 0
            if (z0 + 1 > RES - 1) wz = 0.f;
            wxv[i] = wx; wyv[i] = wy; wzv[i] = wz;

            int rx = (i * RES + y0) * RES + x0 + xh;
            int ry = (i * RES + y1) * RES + x0 + xh;
            int rz =  i * RES + z0 + xh;
            av[i] = GP[rx * 16 + c4];
            bv[i] = GP[ry * 16 + c4];
            lv[i] = GL[rz * 16 + c4];
        }

#pragma unroll
        for (int i = 0; i < 3; i++) {
            float hx = xh ? wxv[i] : 1.f - wxv[i];
            float hz = xh ? wzv[i] : 1.f - wzv[i];
            float wy1 = wyv[i], wy0 = 1.f - wy1;

            float4 t, u;
            t.x = hx * (av[i].x * wy0 + bv[i].x * wy1);
            t.y = hx * (av[i].y * wy0 + bv[i].y * wy1);
            t.z = hx * (av[i].z * wy0 + bv[i].z * wy1);
            t.w = hx * (av[i].w * wy0 + bv[i].w * wy1);
            u.x = hz * lv[i].x;
            u.y = hz * lv[i].y;
            u.z = hz * lv[i].z;
            u.w = hz * lv[i].w;

            t.x += __shfl_xor_sync(0xffffffffu, t.x, 16);
            t.y += __shfl_xor_sync(0xffffffffu, t.y, 16);
            t.z += __shfl_xor_sync(0xffffffffu, t.z, 16);
            t.w += __shfl_xor_sync(0xffffffffu, t.w, 16);
            u.x += __shfl_xor_sync(0xffffffffu, u.x, 16);
            u.y += __shfl_xor_sync(0xffffffffu, u.y, 16);
            u.z += __shfl_xor_sync(0xffffffffu, u.z, 16);
            u.w += __shfl_xor_sync(0xffffffffu, u.w, 16);

            if (xh == 0) {
                float4 f;
                f.x = t.x * u.x; f.y = t.y * u.y;
                f.z = t.z * u.z; f.w = t.w * u.w;
                F4[s * F_ROW4 + i * 16 + c4] = f;
            }
        }
    }
    __syncthreads();

    // ---- phase 2: projection, 4 threads per sample ----
    {
        const int s = tid >> 2;         // 0..63
        const int q = tid & 3;          // output-column group
        const float4* Wq4 = (const float4*)(sm + WQ_OFF + q * WQ_SEC);

        float acc[8];
#pragma unroll
        for (int e = 0; e < 8; e++) acc[e] = 0.f;
        float sig = 0.f;

#pragma unroll
        for (int i = 0; i < 3; i++) {
            const int fb = s * F_ROW4 + i * 16;
#pragma unroll
            for (int c4i = 0; c4i < NC_A / 4; c4i++) {
                float4 f = F4[fb + c4i];
                int j = (i * NC_A + c4i * 4) * 2;   // float4 index of W row
                float4 w0, w1;
                w0 = Wq4[j + 0]; w1 = Wq4[j + 1];
                acc[0] += f.x * w0.x; acc[1] += f.x * w0.y;
                acc[2] += f.x * w0.z; acc[3] += f.x * w0.w;
                acc[4] += f.x * w1.x; acc[5] += f.x * w1.y;
                acc[6] += f.x * w1.z; acc[7] += f.x * w1.w;
                w0 = Wq4[j + 2]; w1 = Wq4[j + 3];
                acc[0] += f.y * w0.x; acc[1] += f.y * w0.y;
                acc[2] += f.y * w0.z; acc[3] += f.y * w0.w;
                acc[4] += f.y * w1.x; acc[5] += f.y * w1.y;
                acc[6] += f.y * w1.z; acc[7] += f.y * w1.w;
                w0 = Wq4[j + 4]; w1 = Wq4[j + 5];
                acc[0] += f.z * w0.x; acc[1] += f.z * w0.y;
                acc[2] += f.z * w0.z; acc[3] += f.z * w0.w;
                acc[4] += f.z * w1.x; acc[5] += f.z * w1.y;
                acc[6] += f.z * w1.z; acc[7] += f.z * w1.w;
                w0 = Wq4[j + 6]; w1 = Wq4[j + 7];
                acc[0] += f.w * w0.x; acc[1] += f.w * w0.y;
                acc[2] += f.w * w0.z; acc[3] += f.w * w0.w;
                acc[4] += f.w * w1.x; acc[5] += f.w * w1.y;
                acc[6] += f.w * w1.z; acc[7] += f.w * w1.w;
            }
            // density: thread q sums quad 12+q
            float4 fd = F4[fb + NC_A / 4 + q];
            sig += fd.x + fd.y + fd.z + fd.w;
        }
        sig += __shfl_xor_sync(0xffffffffu, sig, 1);
        sig += __shfl_xor_sync(0xffffffffu, sig, 2);

        long n = base + s;
        if (n < N) {
            if (q == 0) out[n] = sig;
            float* ao = out + N + n * APP_DIM + q * 7;
            int cnt = (q == 3) ? 6 : 7;
#pragma unroll
            for (int e = 0; e < 7; e++)
                if (e < cnt) ao[e] = acc[e];
        }
    }
}

extern "C" void kernel_launch(void* const* d_in, const int* in_sizes, int n_in,
                              void* d_out, int out_size) {
    const float* xyz   = (const float*)d_in[0];   // (N, 3)
    const float* plane = (const float*)d_in[1];   // (3, 64, 300, 300)
    const float* line  = (const float*)d_in[2];   // (3, 64, 300, 1)
    const float* W     = (const float*)d_in[3];   // (27, 144)
    float* out = (float*)d_out;
    int N = in_sizes[0] / 3;

    transpose_kernel<<<dim3(3 * RES, 11), 256>>>(plane, line);

    int smem_bytes = SMEM_FLOATS * (int)sizeof(float);   // 69440
    cudaFuncSetAttribute(fused_kernel,
                         cudaFuncAttributeMaxDynamicSharedMemorySize, smem_bytes);
    int grid = (N + SPB - 1) / SPB;
    fused_kernel<<<grid, BLOCK, smem_bytes>>>(xyz, W, out, N);
}

// round 5
// speedup vs baseline: 1.6223x; 1.6223x over previous
#include <cuda_runtime.h>

#define RES 300
#define NCH 64            // NC_A + NC_D
#define NC_A 48
#define APP_DIM 27
#define SPB 128           // samples per block
#define BLOCK 128

// Scratch (zero-initialized device globals; pads never written -> stay 0)
__device__ float g_plane_t[3 * RES * RES * NCH + 64];  // (i, h, w, c) + pad
__device__ float g_line_t[3 * RES * NCH + 64];         // (i, h, c)    + pad

// ---------------------------------------------------------------------------
// Merged transpose: plane (3,64,300,300)->(3,300,300,64), line -> (3,300,64)
// ---------------------------------------------------------------------------
__global__ void transpose_kernel(const float* __restrict__ plane,
                                 const float* __restrict__ line) {
    int ih = blockIdx.x;            // 0..899
    int i = ih / RES, h = ih % RES;

    if (blockIdx.y == 10) {
        if (threadIdx.x < NCH)
            g_line_t[((size_t)i * RES + h) * NCH + threadIdx.x] =
                line[((size_t)i * NCH + threadIdx.x) * RES + h];
        return;
    }

    int w0 = blockIdx.y * 30;
    __shared__ float tile[NCH][31];

    for (int idx = threadIdx.x; idx < NCH * 30; idx += blockDim.x) {
        int c = idx / 30, w = idx % 30;
        tile[c][w] = plane[(((size_t)i * NCH + c) * RES + h) * RES + w0 + w];
    }
    __syncthreads();
    float* dst = g_plane_t + (((size_t)i * RES + h) * RES + w0) * NCH;
    for (int idx = threadIdx.x; idx < NCH * 30; idx += blockDim.x) {
        int w = idx / NCH, c = idx % NCH;
        dst[(size_t)w * NCH + c] = tile[c][w];
    }
}

// ---------------------------------------------------------------------------
// Fused kernel, mode-split 3-phase pipeline:
//   for i in 0..2:
//     gather_i : 16-lane group per sample, 6 in-lane corner loads, blend -> F
//     project_i: thread-per-sample, W warp-broadcast from smem, acc in regs
// smem (floats): xyz[384] | W[144][28] | F[128][68]
//   52.5 KB/block -> 4 blocks/SM (16 warps)
// ---------------------------------------------------------------------------
#define XYZ_OFF 0
#define W_OFF   (3 * SPB)                       // 384
#define F_OFF   (W_OFF + 144 * 28)              // 4416
#define F_ROW4  17                              // 68 floats / 4
#define SMEM_FLOATS (F_OFF + SPB * 68)          // 13120 -> 52480 bytes

__global__ void __launch_bounds__(BLOCK, 4)
fused_kernel(const float* __restrict__ xyz,
             const float* __restrict__ basisW,   // (27, 144) row-major
             float* __restrict__ out, int N)
{
    extern __shared__ __align__(16) float sm[];
    float*  xyzsm = sm + XYZ_OFF;
    float*  Wsm   = sm + W_OFF;
    float4* F4    = (float4*)(sm + F_OFF);

    const int tid = threadIdx.x;
    const long base = (long)blockIdx.x * SPB;

    // ---- phase 0: stage xyz + W (broadcast layout, zero pad col) ----
    for (int idx = tid; idx < 3 * SPB; idx += BLOCK) {
        long g = base * 3 + idx;
        xyzsm[idx] = (g < (long)3 * N) ? xyz[g] : 0.f;
    }
    for (int idx = tid; idx < APP_DIM * 144; idx += BLOCK) {
        int d = idx / 144, j = idx - d * 144;
        Wsm[j * 28 + d] = basisW[idx];           // coalesced global read
    }
    if (tid < 144) Wsm[tid * 28 + 27] = 0.f;
    __syncthreads();

    const float4* GP = (const float4*)g_plane_t;
    const float4* GL = (const float4*)g_line_t;
    const int c4   = tid & 15;          // channel quad within 16-lane group
    const int half = (tid >> 4) & 1;    // which sample of the warp's pair
    const int wrp  = tid >> 5;          // 0..3

    float acc[APP_DIM + 1];
#pragma unroll
    for (int d = 0; d < APP_DIM + 1; d++) acc[d] = 0.f;
    float sigma = 0.f;

#pragma unroll
    for (int i = 0; i < 3; i++) {
        // ---- gather_i: 16-lane group per sample ----
#pragma unroll 2
        for (int k = 0; k < SPB / 8; k++) {
            int s = k * 8 + wrp * 2 + half;
            float cx = xyzsm[s * 3 + 0];
            float cy = xyzsm[s * 3 + 1];
            float cz = xyzsm[s * 3 + 2];
            // MAT_MODE = {0,1},{0,2},{1,2}; VEC_MODE = {2,1,0}
            float gx = (i == 2) ? cy : cx;
            float gy = (i == 0) ? cy : cz;
            float gz = (i == 0) ? cz : ((i == 1) ? cy : cx);

            float ix = (gx + 1.f) * 0.5f * (float)(RES - 1);
            float iy = (gy + 1.f) * 0.5f * (float)(RES - 1);
            float iz = (gz + 1.f) * 0.5f * (float)(RES - 1);
            float x0f = floorf(ix), y0f = floorf(iy), z0f = floorf(iz);
            int x0 = (int)x0f, y0 = (int)y0f, z0 = (int)z0f;
            float wx = ix - x0f, wy = iy - y0f, wz = iz - z0f;
            int y1 = y0 + 1;
            if (y1 > RES - 1) { y1 = RES - 1; wy = 0.f; }
            // x/z +1 may read one quad past the row (pad/garbage): weight 0
            if (x0 + 1 > RES - 1) wx = 0.f;
            if (z0 + 1 > RES - 1) wz = 0.f;

            int r0 = (i * RES + y0) * RES + x0;
            int r1 = (i * RES + y1) * RES + x0;
            int rl =  i * RES + z0;
            float4 a00 = GP[r0 * 16 + c4];
            float4 a01 = GP[(r0 + 1) * 16 + c4];
            float4 a10 = GP[r1 * 16 + c4];
            float4 a11 = GP[(r1 + 1) * 16 + c4];
            float4 l0  = GL[rl * 16 + c4];
            float4 l1  = GL[(rl + 1) * 16 + c4];

            float w00 = (1.f - wx) * (1.f - wy);
            float w01 = wx * (1.f - wy);
            float w10 = (1.f - wx) * wy;
            float w11 = wx * wy;
            float wl0 = 1.f - wz, wl1 = wz;

            float4 f;
            f.x = (w00*a00.x + w01*a01.x + w10*a10.x + w11*a11.x) * (wl0*l0.x + wl1*l1.x);
            f.y = (w00*a00.y + w01*a01.y + w10*a10.y + w11*a11.y) * (wl0*l0.y + wl1*l1.y);
            f.z = (w00*a00.z + w01*a01.z + w10*a10.z + w11*a11.z) * (wl0*l0.z + wl1*l1.z);
            f.w = (w00*a00.w + w01*a01.w + w10*a10.w + w11*a11.w) * (wl0*l0.w + wl1*l1.w);

            F4[s * F_ROW4 + c4] = f;
        }
        __syncthreads();

        // ---- project_i: thread-per-sample, W broadcast ----
        {
            const int s = tid;
            const int fb = s * F_ROW4;
            const float* wb = Wsm + i * NC_A * 28;

#pragma unroll 2
            for (int c4i = 0; c4i < NC_A / 4; c4i++) {
                float4 f = F4[fb + c4i];
                const float* q0 = wb + c4i * 4 * 28;
                const float* q1 = q0 + 28;
                const float* q2 = q0 + 56;
                const float* q3 = q0 + 84;
#pragma unroll
                for (int d4 = 0; d4 < 7; d4++) {
                    float4 v0 = *(const float4*)(q0 + d4 * 4);
                    float4 v1 = *(const float4*)(q1 + d4 * 4);
                    float4 v2 = *(const float4*)(q2 + d4 * 4);
                    float4 v3 = *(const float4*)(q3 + d4 * 4);
                    acc[d4*4+0] += f.x*v0.x + f.y*v1.x + f.z*v2.x + f.w*v3.x;
                    acc[d4*4+1] += f.x*v0.y + f.y*v1.y + f.z*v2.y + f.w*v3.y;
                    acc[d4*4+2] += f.x*v0.z + f.y*v1.z + f.z*v2.z + f.w*v3.z;
                    acc[d4*4+3] += f.x*v0.w + f.y*v1.w + f.z*v2.w + f.w*v3.w;
                }
            }
#pragma unroll
            for (int c4i = NC_A / 4; c4i < NCH / 4; c4i++) {
                float4 f = F4[fb + c4i];
                sigma += f.x + f.y + f.z + f.w;
            }
        }
        if (i < 2) __syncthreads();     // F reused next mode
    }

    // ---- write out ----
    long n = base + tid;
    if (n < N) {
        out[n] = sigma;
        float* ao = out + N + n * APP_DIM;
#pragma unroll
        for (int d = 0; d < APP_DIM; d++) ao[d] = acc[d];
    }
}

extern "C" void kernel_launch(void* const* d_in, const int* in_sizes, int n_in,
                              void* d_out, int out_size) {
    const float* xyz   = (const float*)d_in[0];   // (N, 3)
    const float* plane = (const float*)d_in[1];   // (3, 64, 300, 300)
    const float* line  = (const float*)d_in[2];   // (3, 64, 300, 1)
    const float* W     = (const float*)d_in[3];   // (27, 144)
    float* out = (float*)d_out;
    int N = in_sizes[0] / 3;

    transpose_kernel<<<dim3(3 * RES, 11), 256>>>(plane, line);

    int smem_bytes = SMEM_FLOATS * (int)sizeof(float);   // 52480
    cudaFuncSetAttribute(fused_kernel,
                         cudaFuncAttributeMaxDynamicSharedMemorySize, smem_bytes);
    int grid = (N + SPB - 1) / SPB;
    fused_kernel<<<grid, BLOCK, smem_bytes>>>(xyz, W, out, N);
}

// round 6
// speedup vs baseline: 1.7009x; 1.0485x over previous
#include <cuda_runtime.h>

#define RES 300
#define NCH 64            // NC_A + NC_D
#define NC_A 48
#define APP_DIM 27
#define SPB 128           // samples per block
#define BLOCK 128

typedef unsigned long long u64;

__device__ __forceinline__ u64 fma2(u64 a, u64 b, u64 c) {
    u64 d; asm("fma.rn.f32x2 %0, %1, %2, %3;" : "=l"(d) : "l"(a), "l"(b), "l"(c));
    return d;
}
__device__ __forceinline__ u64 mul2(u64 a, u64 b) {
    u64 d; asm("mul.rn.f32x2 %0, %1, %2;" : "=l"(d) : "l"(a), "l"(b));
    return d;
}
__device__ __forceinline__ u64 add2(u64 a, u64 b) {
    u64 d; asm("add.rn.f32x2 %0, %1, %2;" : "=l"(d) : "l"(a), "l"(b));
    return d;
}
__device__ __forceinline__ u64 pack2(float x) {
    u64 d; asm("mov.b64 %0, {%1, %1};" : "=l"(d) : "f"(x));
    return d;
}
__device__ __forceinline__ float lo32(u64 v) {
    return __uint_as_float((unsigned)(v & 0xffffffffULL));
}
__device__ __forceinline__ float hi32(u64 v) {
    return __uint_as_float((unsigned)(v >> 32));
}

// Scratch (zero-initialized device globals; pads never written -> stay 0)
__device__ float g_plane_t[3 * RES * RES * NCH + 64];  // (i, h, w, c) + pad
__device__ float g_line_t[3 * RES * NCH + 64];         // (i, h, c)    + pad

// ---------------------------------------------------------------------------
// Merged transpose: plane (3,64,300,300)->(3,300,300,64), line -> (3,300,64)
// ---------------------------------------------------------------------------
__global__ void transpose_kernel(const float* __restrict__ plane,
                                 const float* __restrict__ line) {
    int ih = blockIdx.x;            // 0..899
    int i = ih / RES, h = ih % RES;

    if (blockIdx.y == 10) {
        if (threadIdx.x < NCH)
            g_line_t[((size_t)i * RES + h) * NCH + threadIdx.x] =
                line[((size_t)i * NCH + threadIdx.x) * RES + h];
        return;
    }

    int w0 = blockIdx.y * 30;
    __shared__ float tile[NCH][31];

    for (int idx = threadIdx.x; idx < NCH * 30; idx += blockDim.x) {
        int c = idx / 30, w = idx % 30;
        tile[c][w] = plane[(((size_t)i * NCH + c) * RES + h) * RES + w0 + w];
    }
    __syncthreads();
    float* dst = g_plane_t + (((size_t)i * RES + h) * RES + w0) * NCH;
    for (int idx = threadIdx.x; idx < NCH * 30; idx += blockDim.x) {
        int w = idx / NCH, c = idx % NCH;
        dst[(size_t)w * NCH + c] = tile[c][w];
    }
}

// ---------------------------------------------------------------------------
// Fused kernel, mode-split 3-phase pipeline, f32x2 packed math:
//   for i in 0..2:
//     gather_i : 16-lane group per sample, 6 in-lane corner loads, f32x2 blend
//     project_i: thread-per-sample, W warp-broadcast LDS.128, f32x2 FMA
// smem (floats): xyz[384] | W[144][28] | F[128][68]  (52.5 KB -> 4 blocks/SM)
// ---------------------------------------------------------------------------
#define XYZ_OFF 0
#define W_OFF   (3 * SPB)                       // 384
#define F_OFF   (W_OFF + 144 * 28)              // 4416
#define F_ROW2  17                              // 68 floats / 4 = 17 (16B units)
#define SMEM_FLOATS (F_OFF + SPB * 68)          // 13120 -> 52480 bytes

__global__ void __launch_bounds__(BLOCK, 4)
fused_kernel(const float* __restrict__ xyz,
             const float* __restrict__ basisW,   // (27, 144) row-major
             float* __restrict__ out, int N)
{
    extern __shared__ __align__(16) float sm[];
    float*      xyzsm = sm + XYZ_OFF;
    float*      Wsm   = sm + W_OFF;
    ulonglong2* F2    = (ulonglong2*)(sm + F_OFF);

    const int tid = threadIdx.x;
    const long base = (long)blockIdx.x * SPB;

    // ---- phase 0: stage xyz + W (broadcast layout, zero pad col) ----
    for (int idx = tid; idx < 3 * SPB; idx += BLOCK) {
        long g = base * 3 + idx;
        xyzsm[idx] = (g < (long)3 * N) ? xyz[g] : 0.f;
    }
    for (int idx = tid; idx < APP_DIM * 144; idx += BLOCK) {
        int d = idx / 144, j = idx - d * 144;
        Wsm[j * 28 + d] = basisW[idx];           // coalesced global read
    }
    if (tid < 144) Wsm[tid * 28 + 27] = 0.f;
    __syncthreads();

    const ulonglong2* GP = (const ulonglong2*)g_plane_t;
    const ulonglong2* GL = (const ulonglong2*)g_line_t;
    const int c4   = tid & 15;          // channel quad within 16-lane group
    const int half = (tid >> 4) & 1;    // which sample of the warp's pair
    const int wrp  = tid >> 5;          // 0..3

    u64 acc2[14];
#pragma unroll
    for (int k = 0; k < 14; k++) acc2[k] = 0ULL;
    u64 sig2 = 0ULL;

#pragma unroll
    for (int i = 0; i < 3; i++) {
        // ---- gather_i: 16-lane group per sample, f32x2 blend ----
#pragma unroll 2
        for (int k = 0; k < SPB / 8; k++) {
            int s = k * 8 + wrp * 2 + half;
            float cx = xyzsm[s * 3 + 0];
            float cy = xyzsm[s * 3 + 1];
            float cz = xyzsm[s * 3 + 2];
            // MAT_MODE = {0,1},{0,2},{1,2}; VEC_MODE = {2,1,0}
            float gx = (i == 2) ? cy : cx;
            float gy = (i == 0) ? cy : cz;
            float gz = (i == 0) ? cz : ((i == 1) ? cy : cx);

            float ix = (gx + 1.f) * 0.5f * (float)(RES - 1);
            float iy = (gy + 1.f) * 0.5f * (float)(RES - 1);
            float iz = (gz + 1.f) * 0.5f * (float)(RES - 1);
            float x0f = floorf(ix), y0f = floorf(iy), z0f = floorf(iz);
            int x0 = (int)x0f, y0 = (int)y0f, z0 = (int)z0f;
            float wx = ix - x0f, wy = iy - y0f, wz = iz - z0f;
            int y1 = y0 + 1;
            if (y1 > RES - 1) { y1 = RES - 1; wy = 0.f; }
            // x/z +1 may read one quad past the row (pad): weight 0
            if (x0 + 1 > RES - 1) wx = 0.f;
            if (z0 + 1 > RES - 1) wz = 0.f;

            int r0 = (i * RES + y0) * RES + x0;
            int r1 = (i * RES + y1) * RES + x0;
            int rl =  i * RES + z0;
            ulonglong2 a00 = GP[r0 * 16 + c4];
            ulonglong2 a01 = GP[(r0 + 1) * 16 + c4];
            ulonglong2 a10 = GP[r1 * 16 + c4];
            ulonglong2 a11 = GP[(r1 + 1) * 16 + c4];
            ulonglong2 l0  = GL[rl * 16 + c4];
            ulonglong2 l1  = GL[(rl + 1) * 16 + c4];

            u64 w00p = pack2((1.f - wx) * (1.f - wy));
            u64 w01p = pack2(wx * (1.f - wy));
            u64 w10p = pack2((1.f - wx) * wy);
            u64 w11p = pack2(wx * wy);
            u64 wl0p = pack2(1.f - wz);
            u64 wl1p = pack2(wz);

            ulonglong2 f;
            u64 t, u;
            t = fma2(w00p, a00.x, fma2(w01p, a01.x,
                 fma2(w10p, a10.x, mul2(w11p, a11.x))));
            u = fma2(wl0p, l0.x, mul2(wl1p, l1.x));
            f.x = mul2(t, u);
            t = fma2(w00p, a00.y, fma2(w01p, a01.y,
                 fma2(w10p, a10.y, mul2(w11p, a11.y))));
            u = fma2(wl0p, l0.y, mul2(wl1p, l1.y));
            f.y = mul2(t, u);

            F2[s * F_ROW2 + c4] = f;
        }
        __syncthreads();

        // ---- project_i: thread-per-sample, W broadcast, f32x2 FMA ----
        {
            const int s = tid;
            const int fb = s * F_ROW2;
            const float* wb = Wsm + i * NC_A * 28;

#pragma unroll 2
            for (int c4i = 0; c4i < NC_A / 4; c4i++) {
                float4 f = ((const float4*)F2)[fb + c4i];
                u64 fx = pack2(f.x), fy = pack2(f.y);
                u64 fz = pack2(f.z), fw = pack2(f.w);
                const ulonglong2* q0 = (const ulonglong2*)(wb + c4i * 4 * 28);
                const ulonglong2* q1 = (const ulonglong2*)(wb + c4i * 4 * 28 + 28);
                const ulonglong2* q2 = (const ulonglong2*)(wb + c4i * 4 * 28 + 56);
                const ulonglong2* q3 = (const ulonglong2*)(wb + c4i * 4 * 28 + 84);
#pragma unroll
                for (int p = 0; p < 7; p++) {
                    ulonglong2 v0 = q0[p], v1 = q1[p], v2 = q2[p], v3 = q3[p];
                    acc2[2*p]   = fma2(fx, v0.x, acc2[2*p]);
                    acc2[2*p+1] = fma2(fx, v0.y, acc2[2*p+1]);
                    acc2[2*p]   = fma2(fy, v1.x, acc2[2*p]);
                    acc2[2*p+1] = fma2(fy, v1.y, acc2[2*p+1]);
                    acc2[2*p]   = fma2(fz, v2.x, acc2[2*p]);
                    acc2[2*p+1] = fma2(fz, v2.y, acc2[2*p+1]);
                    acc2[2*p]   = fma2(fw, v3.x, acc2[2*p]);
                    acc2[2*p+1] = fma2(fw, v3.y, acc2[2*p+1]);
                }
            }
#pragma unroll
            for (int c4i = NC_A / 4; c4i < NCH / 4; c4i++) {
                ulonglong2 fd = F2[fb + c4i];
                sig2 = add2(sig2, add2(fd.x, fd.y));
            }
        }
        if (i < 2) __syncthreads();     // F reused next mode
    }

    // ---- write out ----
    long n = base + tid;
    if (n < N) {
        out[n] = lo32(sig2) + hi32(sig2);
        float* ao = out + N + n * APP_DIM;
#pragma unroll
        for (int p = 0; p < 13; p++) {
            ao[2*p]   = lo32(acc2[p]);
            ao[2*p+1] = hi32(acc2[p]);
        }
        ao[26] = lo32(acc2[13]);
    }
}

extern "C" void kernel_launch(void* const* d_in, const int* in_sizes, int n_in,
                              void* d_out, int out_size) {
    const float* xyz   = (const float*)d_in[0];   // (N, 3)
    const float* plane = (const float*)d_in[1];   // (3, 64, 300, 300)
    const float* line  = (const float*)d_in[2];   // (3, 64, 300, 1)
    const float* W     = (const float*)d_in[3];   // (27, 144)
    float* out = (float*)d_out;
    int N = in_sizes[0] / 3;

    transpose_kernel<<<dim3(3 * RES, 11), 256>>>(plane, line);

    int smem_bytes = SMEM_FLOATS * (int)sizeof(float);   // 52480
    cudaFuncSetAttribute(fused_kernel,
                         cudaFuncAttributeMaxDynamicSharedMemorySize, smem_bytes);
    int grid = (N + SPB - 1) / SPB;
    fused_kernel<<<grid, BLOCK, smem_bytes>>>(xyz, W, out, N);
}

// round 7
// speedup vs baseline: 1.7031x; 1.0013x over previous
#include <cuda_runtime.h>

#define RES 300
#define NCH 64            // NC_A + NC_D
#define NC_A 48
#define APP_DIM 27
#define SPB 128           // samples per block
#define BLOCK 128

typedef unsigned long long u64;

__device__ __forceinline__ u64 fma2(u64 a, u64 b, u64 c) {
    u64 d; asm("fma.rn.f32x2 %0, %1, %2, %3;" : "=l"(d) : "l"(a), "l"(b), "l"(c));
    return d;
}
__device__ __forceinline__ u64 mul2(u64 a, u64 b) {
    u64 d; asm("mul.rn.f32x2 %0, %1, %2;" : "=l"(d) : "l"(a), "l"(b));
    return d;
}
__device__ __forceinline__ u64 add2(u64 a, u64 b) {
    u64 d; asm("add.rn.f32x2 %0, %1, %2;" : "=l"(d) : "l"(a), "l"(b));
    return d;
}
__device__ __forceinline__ u64 pack2(float x) {
    u64 d; asm("mov.b64 %0, {%1, %1};" : "=l"(d) : "f"(x));
    return d;
}
__device__ __forceinline__ float lo32(u64 v) {
    return __uint_as_float((unsigned)(v & 0xffffffffULL));
}
__device__ __forceinline__ float hi32(u64 v) {
    return __uint_as_float((unsigned)(v >> 32));
}

// Scratch (zero-initialized device globals; pads never written -> stay 0)
__device__ float g_plane_t[3 * RES * RES * NCH + 64];  // (i, h, w, c) + pad
__device__ float g_line_t[3 * RES * NCH + 64];         // (i, h, c)    + pad

// ---------------------------------------------------------------------------
// Merged transpose: plane (3,64,300,300)->(3,300,300,64), line -> (3,300,64)
// ---------------------------------------------------------------------------
__global__ void transpose_kernel(const float* __restrict__ plane,
                                 const float* __restrict__ line) {
    int ih = blockIdx.x;            // 0..899
    int i = ih / RES, h = ih % RES;

    if (blockIdx.y == 10) {
        if (threadIdx.x < NCH)
            g_line_t[((size_t)i * RES + h) * NCH + threadIdx.x] =
                line[((size_t)i * NCH + threadIdx.x) * RES + h];
        return;
    }

    int w0 = blockIdx.y * 30;
    __shared__ float tile[NCH][31];

    for (int idx = threadIdx.x; idx < NCH * 30; idx += blockDim.x) {
        int c = idx / 30, w = idx % 30;
        tile[c][w] = plane[(((size_t)i * NCH + c) * RES + h) * RES + w0 + w];
    }
    __syncthreads();
    float* dst = g_plane_t + (((size_t)i * RES + h) * RES + w0) * NCH;
    for (int idx = threadIdx.x; idx < NCH * 30; idx += blockDim.x) {
        int w = idx / NCH, c = idx % NCH;
        dst[(size_t)w * NCH + c] = tile[c][w];
    }
}

// ---------------------------------------------------------------------------
// Fused kernel, mode-split 3-phase pipeline, f32x2 packed math:
//   for i in 0..2:
//     gather_i : 16-lane group per sample, 6 in-lane corner loads, f32x2 blend
//     project_i: thread-per-sample, W warp-broadcast LDS.128, f32x2 FMA
// smem (floats): xyz[384] | W[144][28] | F[128][68]  (52.5 KB -> 4 blocks/SM)
// ---------------------------------------------------------------------------
#define XYZ_OFF 0
#define W_OFF   (3 * SPB)                       // 384
#define F_OFF   (W_OFF + 144 * 28)              // 4416
#define F_ROW2  17                              // 68 floats / 4 = 17 (16B units)
#define SMEM_FLOATS (F_OFF + SPB * 68)          // 13120 -> 52480 bytes

__global__ void __launch_bounds__(BLOCK, 4)
fused_kernel(const float* __restrict__ xyz,
             const float* __restrict__ basisW,   // (27, 144) row-major
             float* __restrict__ out, int N)
{
    extern __shared__ __align__(16) float sm[];
    float*      xyzsm = sm + XYZ_OFF;
    float*      Wsm   = sm + W_OFF;
    ulonglong2* F2    = (ulonglong2*)(sm + F_OFF);

    const int tid = threadIdx.x;
    const long base = (long)blockIdx.x * SPB;

    // ---- phase 0: stage xyz + W (broadcast layout, zero pad col) ----
    for (int idx = tid; idx < 3 * SPB; idx += BLOCK) {
        long g = base * 3 + idx;
        xyzsm[idx] = (g < (long)3 * N) ? xyz[g] : 0.f;
    }
    for (int idx = tid; idx < APP_DIM * 144; idx += BLOCK) {
        int d = idx / 144, j = idx - d * 144;
        Wsm[j * 28 + d] = basisW[idx];           // coalesced global read
    }
    if (tid < 144) Wsm[tid * 28 + 27] = 0.f;
    __syncthreads();

    const ulonglong2* GP = (const ulonglong2*)g_plane_t;
    const ulonglong2* GL = (const ulonglong2*)g_line_t;
    const int c4   = tid & 15;          // channel quad within 16-lane group
    const int half = (tid >> 4) & 1;    // which sample of the warp's pair
    const int wrp  = tid >> 5;          // 0..3

    u64 acc2[14];
#pragma unroll
    for (int k = 0; k < 14; k++) acc2[k] = 0ULL;
    u64 sig2 = 0ULL;

#pragma unroll
    for (int i = 0; i < 3; i++) {
        // ---- gather_i: 16-lane group per sample, f32x2 blend ----
#pragma unroll 2
        for (int k = 0; k < SPB / 8; k++) {
            int s = k * 8 + wrp * 2 + half;
            float cx = xyzsm[s * 3 + 0];
            float cy = xyzsm[s * 3 + 1];
            float cz = xyzsm[s * 3 + 2];
            // MAT_MODE = {0,1},{0,2},{1,2}; VEC_MODE = {2,1,0}
            float gx = (i == 2) ? cy : cx;
            float gy = (i == 0) ? cy : cz;
            float gz = (i == 0) ? cz : ((i == 1) ? cy : cx);

            float ix = (gx + 1.f) * 0.5f * (float)(RES - 1);
            float iy = (gy + 1.f) * 0.5f * (float)(RES - 1);
            float iz = (gz + 1.f) * 0.5f * (float)(RES - 1);
            float x0f = floorf(ix), y0f = floorf(iy), z0f = floorf(iz);
            int x0 = (int)x0f, y0 = (int)y0f, z0 = (int)z0f;
            float wx = ix - x0f, wy = iy - y0f, wz = iz - z0f;
            int y1 = y0 + 1;
            if (y1 > RES - 1) { y1 = RES - 1; wy = 0.f; }
            // x/z +1 may read one quad past the row (pad): weight 0
            if (x0 + 1 > RES - 1) wx = 0.f;
            if (z0 + 1 > RES - 1) wz = 0.f;

            int r0 = (i * RES + y0) * RES + x0;
            int r1 = (i * RES + y1) * RES + x0;
            int rl =  i * RES + z0;
            ulonglong2 a00 = GP[r0 * 16 + c4];
            ulonglong2 a01 = GP[(r0 + 1) * 16 + c4];
            ulonglong2 a10 = GP[r1 * 16 + c4];
            ulonglong2 a11 = GP[(r1 + 1) * 16 + c4];
            ulonglong2 l0  = GL[rl * 16 + c4];
            ulonglong2 l1  = GL[(rl + 1) * 16 + c4];

            u64 w00p = pack2((1.f - wx) * (1.f - wy));
            u64 w01p = pack2(wx * (1.f - wy));
            u64 w10p = pack2((1.f - wx) * wy);
            u64 w11p = pack2(wx * wy);
            u64 wl0p = pack2(1.f - wz);
            u64 wl1p = pack2(wz);

            ulonglong2 f;
            u64 t, u;
            t = fma2(w00p, a00.x, fma2(w01p, a01.x,
                 fma2(w10p, a10.x, mul2(w11p, a11.x))));
            u = fma2(wl0p, l0.x, mul2(wl1p, l1.x));
            f.x = mul2(t, u);
            t = fma2(w00p, a00.y, fma2(w01p, a01.y,
                 fma2(w10p, a10.y, mul2(w11p, a11.y))));
            u = fma2(wl0p, l0.y, mul2(wl1p, l1.y));
            f.y = mul2(t, u);

            F2[s * F_ROW2 + c4] = f;
        }
        __syncthreads();

        // ---- project_i: thread-per-sample, W broadcast, f32x2 FMA ----
        {
            const int s = tid;
            const int fb = s * F_ROW2;
            const float* wb = Wsm + i * NC_A * 28;

#pragma unroll 2
            for (int c4i = 0; c4i < NC_A / 4; c4i++) {
                float4 f = ((const float4*)F2)[fb + c4i];
                u64 fx = pack2(f.x), fy = pack2(f.y);
                u64 fz = pack2(f.z), fw = pack2(f.w);
                const ulonglong2* q0 = (const ulonglong2*)(wb + c4i * 4 * 28);
                const ulonglong2* q1 = (const ulonglong2*)(wb + c4i * 4 * 28 + 28);
                const ulonglong2* q2 = (const ulonglong2*)(wb + c4i * 4 * 28 + 56);
                const ulonglong2* q3 = (const ulonglong2*)(wb + c4i * 4 * 28 + 84);
#pragma unroll
                for (int p = 0; p < 7; p++) {
                    ulonglong2 v0 = q0[p], v1 = q1[p], v2 = q2[p], v3 = q3[p];
                    acc2[2*p]   = fma2(fx, v0.x, acc2[2*p]);
                    acc2[2*p+1] = fma2(fx, v0.y, acc2[2*p+1]);
                    acc2[2*p]   = fma2(fy, v1.x, acc2[2*p]);
                    acc2[2*p+1] = fma2(fy, v1.y, acc2[2*p+1]);
                    acc2[2*p]   = fma2(fz, v2.x, acc2[2*p]);
                    acc2[2*p+1] = fma2(fz, v2.y, acc2[2*p+1]);
                    acc2[2*p]   = fma2(fw, v3.x, acc2[2*p]);
                    acc2[2*p+1] = fma2(fw, v3.y, acc2[2*p+1]);
                }
            }
#pragma unroll
            for (int c4i = NC_A / 4; c4i < NCH / 4; c4i++) {
                ulonglong2 fd = F2[fb + c4i];
                sig2 = add2(sig2, add2(fd.x, fd.y));
            }
        }
        if (i < 2) __syncthreads();     // F reused next mode
    }

    // ---- write out ----
    long n = base + tid;
    if (n < N) {
        out[n] = lo32(sig2) + hi32(sig2);
        float* ao = out + N + n * APP_DIM;
#pragma unroll
        for (int p = 0; p < 13; p++) {
            ao[2*p]   = lo32(acc2[p]);
            ao[2*p+1] = hi32(acc2[p]);
        }
        ao[26] = lo32(acc2[13]);
    }
}

extern "C" void kernel_launch(void* const* d_in, const int* in_sizes, int n_in,
                              void* d_out, int out_size) {
    const float* xyz   = (const float*)d_in[0];   // (N, 3)
    const float* plane = (const float*)d_in[1];   // (3, 64, 300, 300)
    const float* line  = (const float*)d_in[2];   // (3, 64, 300, 1)
    const float* W     = (const float*)d_in[3];   // (27, 144)
    float* out = (float*)d_out;
    int N = in_sizes[0] / 3;

    transpose_kernel<<<dim3(3 * RES, 11), 256>>>(plane, line);

    int smem_bytes = SMEM_FLOATS * (int)sizeof(float);   // 52480
    cudaFuncSetAttribute(fused_kernel,
                         cudaFuncAttributeMaxDynamicSharedMemorySize, smem_bytes);
    int grid = (N + SPB - 1) / SPB;
    fused_kernel<<<grid, BLOCK, smem_bytes>>>(xyz, W, out, N);
}